// round 15
// baseline (speedup 1.0000x reference)
#include <cuda_runtime.h>
#include <cuda_bf16.h>
#include <math.h>
#include <stdint.h>

#define CH    96
#define HH    192
#define WWI   192
#define HW    (HH*WWI)        // 36864
#define BATCH 4
#define NWIN_PER 576          // 24*24 windows per image
#define NWIN  (BATCH*NWIN_PER)
#define NTOK  64
#define QS    100             // fp32 row stride (Y)

// 56.6 MB each — static device scratch (no allocations allowed)
__device__ float g_imgA[BATCH*HW*CH];
__device__ float g_imgB[BATCH*HW*CH];

// fragment-packed bf16 weights: per (n_tile, ks) 32 x uint4{bh0,bh1,bl0,bl1}
#define WF_SA1_QKV   0         // 288*96/4 = 6912
#define WF_SA1_PROJ  6912      // 96*96/4  = 2304
#define WF_SA2_QKV   9216
#define WF_SA2_PROJ  16128
#define WF_FF1_W1    18432     // 192*96/4 = 4608
#define WF_FF2_W1    23040
#define WF_FF1_W2    27648     // 96*192/4 = 4608
#define WF_FF2_W2    32256     // -> total 36864
__device__ __align__(16) uint4 g_wfrag[36864];

// precomputed bias+mask: [table(2)][variant(4)][head(6)][i(64)][j(64)]
__device__ __align__(16) float g_bias[2 * 4 * 6 * 64 * 64];

// ---------------------------------------------------------------------------
__device__ __forceinline__ float fexp(float x) {
    x = fmaxf(x, -80.0f);
    const float L2E = 1.4426950408889634f;
    float t = fmaf(x, L2E, 12582912.0f);
    float n = t - 12582912.0f;
    float f = fmaf(x, L2E, -n);
    float p = 1.5403530393381608e-4f;
    p = fmaf(p, f, 1.3333558146428443e-3f);
    p = fmaf(p, f, 9.6181291076284772e-3f);
    p = fmaf(p, f, 5.5504108664821580e-2f);
    p = fmaf(p, f, 2.4022650695910072e-1f);
    p = fmaf(p, f, 6.9314718055994531e-1f);
    p = fmaf(p, f, 1.0f);
    int e = (int)n;
    float s = __int_as_float((127 + e) << 23);
    return p * s;
}

// ---------------------------------------------------------------------------
// bf16 split/reconstruct + m16n8k16 bf16 MMA (3-term: err ~2^-18)
// ---------------------------------------------------------------------------
__device__ __forceinline__ void bfsplit2(float x0, float x1, uint32_t& h2, uint32_t& l2) {
    uint32_t h;
    asm("cvt.rn.bf16x2.f32 %0, %1, %2;" : "=r"(h) : "f"(x1), "f"(x0));
    float h0 = __uint_as_float(h << 16);
    float h1 = __uint_as_float(h & 0xffff0000u);
    uint32_t l;
    asm("cvt.rn.bf16x2.f32 %0, %1, %2;" : "=r"(l) : "f"(x1 - h1), "f"(x0 - h0));
    h2 = h; l2 = l;
}
__device__ __forceinline__ void bfsplit1(float x, __nv_bfloat16& h, __nv_bfloat16& l) {
    h = __float2bfloat16(x);
    l = __float2bfloat16(x - __bfloat162float(h));
}
__device__ __forceinline__ void bfrec2(uint2 w, float& x0, float& x1) {
    x0 = __uint_as_float(w.x << 16)          + __uint_as_float(w.y << 16);
    x1 = __uint_as_float(w.x & 0xffff0000u)  + __uint_as_float(w.y & 0xffff0000u);
}
__device__ __forceinline__ void mma_bf16(float4& d, const uint32_t* a,
                                         uint32_t b0, uint32_t b1) {
    asm volatile("mma.sync.aligned.m16n8k16.row.col.f32.bf16.bf16.f32 "
                 "{%0,%1,%2,%3},{%4,%5,%6,%7},{%8,%9},{%0,%1,%2,%3};"
                 : "+f"(d.x), "+f"(d.y), "+f"(d.z), "+f"(d.w)
                 : "r"(a[0]), "r"(a[1]), "r"(a[2]), "r"(a[3]), "r"(b0), "r"(b1));
}

// C = A(pre-split interleaved uint2 plane [row][kword], stride ldaw)
//   @ B(fragment-packed uint4).
template<int NT, int KST>
__device__ __forceinline__ void mma_gemm_pk(
    float4* acc, const uint2* A, int ldaw, int m0,
    const uint4* __restrict__ Bf, int nt0, int mg, int mt, int tx)
{
    #pragma unroll
    for (int ks = 0; ks < KST; ks++) {
        uint2 a0 = A[(m0 + mg) * ldaw + ks * 8 + mt];
        uint2 a1 = A[(m0 + mg + 8) * ldaw + ks * 8 + mt];
        uint2 a2 = A[(m0 + mg) * ldaw + ks * 8 + 4 + mt];
        uint2 a3 = A[(m0 + mg + 8) * ldaw + ks * 8 + 4 + mt];
        uint32_t ah[4] = {a0.x, a1.x, a2.x, a3.x};
        uint32_t al[4] = {a0.y, a1.y, a2.y, a3.y};
        #pragma unroll
        for (int j = 0; j < NT; j++) {
            uint4 w = __ldg(&Bf[((nt0 + j) * KST + ks) * 32 + tx]);
            mma_bf16(acc[j], ah, w.x, w.y);
            mma_bf16(acc[j], ah, w.z, w.w);
            mma_bf16(acc[j], al, w.x, w.y);
        }
    }
}

// ---------------------------------------------------------------------------
// Weight prep: W[K][N] fp32 -> fragment-packed uint4 per (n_tile, ks, lane).
// ---------------------------------------------------------------------------
__global__ void split_all_weights(
    const float* s0, const float* s1, const float* s2, const float* s3,
    const float* s4, const float* s5, const float* s6, const float* s7)
{
    const int Ks[8]  = {96, 96, 96, 96, 96, 96, 192, 192};
    const int Ns[8]  = {288, 96, 288, 96, 192, 192, 96, 96};
    const int off[8] = {WF_SA1_QKV, WF_SA1_PROJ, WF_SA2_QKV, WF_SA2_PROJ,
                        WF_FF1_W1, WF_FF2_W1, WF_FF1_W2, WF_FF2_W2};
    int m = blockIdx.y;
    int K = Ks[m], N = Ns[m];
    int KST = K / 16;
    int total = (N / 8) * KST * 32;
    int e = blockIdx.x * 256 + threadIdx.x;
    if (e >= total) return;
    const float* src;
    switch (m) {
        case 0: src = s0; break; case 1: src = s1; break;
        case 2: src = s2; break; case 3: src = s3; break;
        case 4: src = s4; break; case 5: src = s5; break;
        case 6: src = s6; break; default: src = s7; break;
    }
    int lane  = e & 31;
    int ks    = (e >> 5) % KST;
    int ntile = e / (32 * KST);
    int mg = lane >> 2, mt = lane & 3;
    int n  = ntile * 8 + mg;
    int k0 = ks * 16;
    float x0 = src[(k0 + 2 * mt)     * N + n];
    float x1 = src[(k0 + 2 * mt + 1) * N + n];
    float x2 = src[(k0 + 8 + 2 * mt)     * N + n];
    float x3 = src[(k0 + 8 + 2 * mt + 1) * N + n];
    uint32_t bh0, bl0, bh1, bl1;
    bfsplit2(x0, x1, bh0, bl0);
    bfsplit2(x2, x3, bh1, bl1);
    g_wfrag[off[m] + e] = make_uint4(bh0, bh1, bl0, bl1);
}

// ---------------------------------------------------------------------------
// Bias prep: table[T][6] -> Bias[table][variant][hd][i][j] with shift mask.
// variant bits: 2 = wr==23, 1 = wc==23.
// ---------------------------------------------------------------------------
__global__ void build_bias(const float* __restrict__ t1, const float* __restrict__ t2) {
    int tb = blockIdx.y;
    int e  = blockIdx.x * 256 + threadIdx.x;  // [0, 98304)
    if (e >= 4 * 6 * 4096) return;
    const float* tab = tb ? t2 : t1;
    int v  = e / 24576;
    int r  = e - v * 24576;
    int hd = r / 4096;
    int ij = r - hd * 4096;
    int i = ij >> 6, j = ij & 63;
    int ri = i >> 3, ci = i & 7, rj = j >> 3, cj = j & 7;
    float bias = tab[((ri - rj + 7) * 15 + (ci - cj + 7)) * 6 + hd];
    int wr23 = v & 2, wc23 = v & 1;
    int cnti = (wr23 ? (ri < 4 ? 1 : 2) : 0) * 3 + (wc23 ? (ci < 4 ? 1 : 2) : 0);
    int cntj = (wr23 ? (rj < 4 ? 1 : 2) : 0) * 3 + (wc23 ? (cj < 4 ? 1 : 2) : 0);
    if (cnti != cntj) bias -= 100.f;
    g_bias[tb * 98304 + e] = bias;
}

// ---------------------------------------------------------------------------
// Transposes: [B,C,H,W] <-> [B,HW,C]
// ---------------------------------------------------------------------------
__global__ void transpose_in_kernel(const float* __restrict__ x, float* __restrict__ img) {
    __shared__ float tile[32][33];
    int b = blockIdx.z;
    int hw0 = blockIdx.x * 32, c0 = blockIdx.y * 32;
    const float* src = x + (size_t)b * CH * HW;
    float* dst = img + (size_t)b * HW * CH;
    #pragma unroll
    for (int i = threadIdx.y; i < 32; i += 8)
        tile[i][threadIdx.x] = src[(size_t)(c0 + i) * HW + hw0 + threadIdx.x];
    __syncthreads();
    #pragma unroll
    for (int i = threadIdx.y; i < 32; i += 8)
        dst[(size_t)(hw0 + i) * CH + c0 + threadIdx.x] = tile[threadIdx.x][i];
}

__global__ void transpose_out_kernel(const float* __restrict__ img, float* __restrict__ x) {
    __shared__ float tile[32][33];
    int b = blockIdx.z;
    int hw0 = blockIdx.x * 32, c0 = blockIdx.y * 32;
    const float* src = img + (size_t)b * HW * CH;
    float* dst = x + (size_t)b * CH * HW;
    #pragma unroll
    for (int i = threadIdx.y; i < 32; i += 8)
        tile[i][threadIdx.x] = src[(size_t)(hw0 + i) * CH + c0 + threadIdx.x];
    __syncthreads();
    #pragma unroll
    for (int i = threadIdx.y; i < 32; i += 8)
        dst[(size_t)(c0 + i) * HW + hw0 + threadIdx.x] = tile[threadIdx.x][i];
}

// ---------------------------------------------------------------------------
// Fused Swin block (attention + FFN) per window. bf16 3-term mma everywhere;
// in-register softmax with two-half online merge; precomputed gmem bias.
// smem (4B words): Y 6400 | stats 128 | ST 512 | XP 6400 | OP 6400 | QP 6400
//   | KP 6400 | SP 8704 | VH 3456 | VL 3456 = 48,256 words = 193,024 B
// FFN: HP (12544 w) overlays QP+KP.
// ---------------------------------------------------------------------------
#define BLK_SMEM 193024

template<int SHIFTED>
__global__ void __launch_bounds__(512, 1) block_kernel(
    const float* __restrict__ in, float* __restrict__ out,
    const uint4* __restrict__ WQF, const float* __restrict__ bqkv,
    const float* __restrict__ BiasT,
    const uint4* __restrict__ WPF, const float* __restrict__ bproj,
    const float* __restrict__ gam1, const float* __restrict__ beta1,
    const uint4* __restrict__ W1F, const float* __restrict__ b1,
    const uint4* __restrict__ W2F, const float* __restrict__ b2,
    const float* __restrict__ gam2, const float* __restrict__ beta2)
{
    extern __shared__ float sm[];
    float*  Y     = sm;                    // 6400 fp32
    float*  stats = Y + 6400;              // 128
    float2* ST    = (float2*)(stats + 128);// 256 float2 (softmax stats)
    uint2*  XP    = (uint2*)(stats + 128 + 512); // 3200 uint2
    uint2*  OP    = XP + 3200;
    uint2*  QP    = OP + 3200;
    uint2*  KP    = QP + 3200;
    uint2*  SP    = KP + 3200;             // 4352 uint2 (2 x 64 x 34)
    uint32_t* VH  = (uint32_t*)(SP + 4352);// 3456 words
    uint32_t* VL  = VH + 3456;
    __nv_bfloat16* VHs = (__nv_bfloat16*)VH;
    __nv_bfloat16* VLs = (__nv_bfloat16*)VL;
    uint2*  HP    = QP;                    // FFN hidden overlays QP+KP

    const int tid = threadIdx.x;
    const int wid = blockIdx.x;
    const int b  = wid / NWIN_PER;
    const int wl = wid - b * NWIN_PER;
    const int wr = wl / 24, wc = wl - (wl / 24) * 24;
    const float* src = in  + (size_t)b * HW * CH;
    float*       dst = out + (size_t)b * HW * CH;
    const int variant = SHIFTED ? (((wr == 23) ? 2 : 0) | ((wc == 23) ? 1 : 0)) : 0;
    const float* BiasV = BiasT + variant * 24576;

    // ---- gather window tokens into split plane XP ----
    for (int idx = tid; idx < 64 * 48; idx += 512) {
        int t = idx / 48, wd = idx - t * 48;
        int r = t >> 3, cl = t & 7;
        int h = wr * 8 + r, w = wc * 8 + cl;
        if (SHIFTED) { h += 4; if (h >= HH) h -= HH; w += 4; if (w >= WWI) w -= WWI; }
        float2 v = *(const float2*)&src[(h * WWI + w) * CH + 2 * wd];
        uint32_t hh, ll;
        bfsplit2(v.x, v.y, hh, ll);
        XP[t * 50 + wd] = make_uint2(hh, ll);
    }
    __syncthreads();

    const int wg = tid >> 5, tx = tid & 31;   // 16 warps
    const int mg = tx >> 2, mt = tx & 3;
    const int m0 = (wg & 3) * 16;
    const int nch = wg >> 2;

    // ================= ATTENTION =================
    // ---- QKV GEMM -> split Q/K planes + transposed V planes ----
    {
        float4 acc[9];
        #pragma unroll
        for (int j = 0; j < 9; j++) {
            int c = nch * 72 + j * 8 + 2 * mt;
            float b0 = __ldg(&bqkv[c]), b1v = __ldg(&bqkv[c + 1]);
            acc[j].x = b0; acc[j].y = b1v; acc[j].z = b0; acc[j].w = b1v;
        }
        mma_gemm_pk<9, 6>(acc, XP, 50, m0, WQF, nch * 9, mg, mt, tx);
        #pragma unroll
        for (int j = 0; j < 9; j++) {
            int cb = nch * 72 + j * 8;
            int c  = cb + 2 * mt;
            int rA = m0 + mg, rB = rA + 8;
            if (cb < 96) {
                int cw = c / 2;
                uint32_t h, l;
                bfsplit2(acc[j].x, acc[j].y, h, l); QP[rA * 50 + cw] = make_uint2(h, l);
                bfsplit2(acc[j].z, acc[j].w, h, l); QP[rB * 50 + cw] = make_uint2(h, l);
            } else if (cb < 192) {
                int cw = (c - 96) / 2;
                uint32_t h, l;
                bfsplit2(acc[j].x, acc[j].y, h, l); KP[rA * 50 + cw] = make_uint2(h, l);
                bfsplit2(acc[j].z, acc[j].w, h, l); KP[rB * 50 + cw] = make_uint2(h, l);
            } else {
                int d = c - 192;
                __nv_bfloat16 h, l;
                bfsplit1(acc[j].x, h, l); VHs[d * 72 + rA] = h;       VLs[d * 72 + rA] = l;
                bfsplit1(acc[j].y, h, l); VHs[(d + 1) * 72 + rA] = h; VLs[(d + 1) * 72 + rA] = l;
                bfsplit1(acc[j].z, h, l); VHs[d * 72 + rB] = h;       VLs[d * 72 + rB] = l;
                bfsplit1(acc[j].w, h, l); VHs[(d + 1) * 72 + rB] = h; VLs[(d + 1) * 72 + rB] = l;
            }
        }
    }
    __syncthreads();

    // ---- heads: 2 in flight; 8 warps/head; in-register softmax ----
    const int hg = wg >> 3;
    const int w8 = wg & 7;
    const int hm = w8 & 3;
    const int nh = w8 >> 2;

    for (int it = 0; it < 3; it++) {
        const int hd = it * 2 + hg;
        uint2* SPg = SP + hg * (64 * 34);

        // scores + bias + in-register softmax -> split SP
        {
            float4 acc[4];
            #pragma unroll
            for (int jt = 0; jt < 4; jt++) acc[jt] = make_float4(0.f, 0.f, 0.f, 0.f);
            int qw = (hm * 16 + mg) * 50 + hd * 8 + mt;
            uint2 q0 = QP[qw], q1 = QP[qw + 400], q2 = QP[qw + 4], q3 = QP[qw + 404];
            uint32_t ah[4] = {q0.x, q1.x, q2.x, q3.x};
            uint32_t al[4] = {q0.y, q1.y, q2.y, q3.y};
            #pragma unroll
            for (int jt = 0; jt < 4; jt++) {
                int kw = (nh * 32 + jt * 8 + mg) * 50 + hd * 8 + mt;
                uint2 b0 = KP[kw], b1v = KP[kw + 4];
                mma_bf16(acc[jt], ah, b0.x, b1v.x);
                mma_bf16(acc[jt], ah, b0.y, b1v.y);
                mma_bf16(acc[jt], al, b0.x, b1v.x);
            }
            const int iA = hm * 16 + mg, iB = iA + 8;
            const float* BP = BiasV + hd * 4096;
            float mA = -1e30f, mB = -1e30f;
            #pragma unroll
            for (int jt = 0; jt < 4; jt++) {
                int c = nh * 32 + jt * 8 + 2 * mt;
                acc[jt].x = fmaf(acc[jt].x, 0.25f, __ldg(&BP[iA * 64 + c]));
                acc[jt].y = fmaf(acc[jt].y, 0.25f, __ldg(&BP[iA * 64 + c + 1]));
                acc[jt].z = fmaf(acc[jt].z, 0.25f, __ldg(&BP[iB * 64 + c]));
                acc[jt].w = fmaf(acc[jt].w, 0.25f, __ldg(&BP[iB * 64 + c + 1]));
                mA = fmaxf(mA, fmaxf(acc[jt].x, acc[jt].y));
                mB = fmaxf(mB, fmaxf(acc[jt].z, acc[jt].w));
            }
            // reduce over mt lanes (lane = mg*4+mt)
            mA = fmaxf(mA, __shfl_xor_sync(0xffffffffu, mA, 1));
            mA = fmaxf(mA, __shfl_xor_sync(0xffffffffu, mA, 2));
            mB = fmaxf(mB, __shfl_xor_sync(0xffffffffu, mB, 1));
            mB = fmaxf(mB, __shfl_xor_sync(0xffffffffu, mB, 2));
            float sA = 0.f, sB = 0.f;
            #pragma unroll
            for (int jt = 0; jt < 4; jt++) {
                acc[jt].x = fexp(acc[jt].x - mA); acc[jt].y = fexp(acc[jt].y - mA);
                acc[jt].z = fexp(acc[jt].z - mB); acc[jt].w = fexp(acc[jt].w - mB);
                sA += acc[jt].x + acc[jt].y;
                sB += acc[jt].z + acc[jt].w;
            }
            sA += __shfl_xor_sync(0xffffffffu, sA, 1);
            sA += __shfl_xor_sync(0xffffffffu, sA, 2);
            sB += __shfl_xor_sync(0xffffffffu, sB, 1);
            sB += __shfl_xor_sync(0xffffffffu, sB, 2);
            if (mt == 0) {
                ST[((hg * 64 + iA) << 1) | nh] = make_float2(mA, sA);
                ST[((hg * 64 + iB) << 1) | nh] = make_float2(mB, sB);
            }
            __syncthreads();
            // merge two halves per row, compute local scale
            float2 pA0 = ST[(hg * 64 + iA) << 1], pA1 = ST[((hg * 64 + iA) << 1) | 1];
            float2 pB0 = ST[(hg * 64 + iB) << 1], pB1 = ST[((hg * 64 + iB) << 1) | 1];
            float MA = fmaxf(pA0.x, pA1.x);
            float SAt = pA0.y * fexp(pA0.x - MA) + pA1.y * fexp(pA1.x - MA);
            float scaleA = fexp(mA - MA) / SAt;
            float MB = fmaxf(pB0.x, pB1.x);
            float SBt = pB0.y * fexp(pB0.x - MB) + pB1.y * fexp(pB1.x - MB);
            float scaleB = fexp(mB - MB) / SBt;
            #pragma unroll
            for (int jt = 0; jt < 4; jt++) {
                int kw = nh * 16 + jt * 4 + mt;
                uint32_t h, l;
                bfsplit2(acc[jt].x * scaleA, acc[jt].y * scaleA, h, l);
                SPg[iA * 34 + kw] = make_uint2(h, l);
                bfsplit2(acc[jt].z * scaleB, acc[jt].w * scaleB, h, l);
                SPg[iB * 34 + kw] = make_uint2(h, l);
            }
        }
        __syncthreads();

        // AV -> split OP
        {
            int nc0 = hd * 16 + nh * 8;
            float4 acc = make_float4(0.f, 0.f, 0.f, 0.f);
            #pragma unroll
            for (int ks = 0; ks < 4; ks++) {
                int spw = (hm * 16 + mg) * 34 + ks * 8 + mt;
                uint2 a0 = SPg[spw],     a1 = SPg[spw + 272];
                uint2 a2 = SPg[spw + 4], a3 = SPg[spw + 276];
                uint32_t ah[4] = {a0.x, a1.x, a2.x, a3.x};
                uint32_t al[4] = {a0.y, a1.y, a2.y, a3.y};
                int vw = (nc0 + mg) * 36 + ks * 8 + mt;
                uint32_t bh0 = VH[vw], bh1 = VH[vw + 4];
                uint32_t bl0 = VL[vw], bl1 = VL[vw + 4];
                mma_bf16(acc, ah, bh0, bh1);
                mma_bf16(acc, ah, bl0, bl1);
                mma_bf16(acc, al, bh0, bh1);
            }
            int rA = hm * 16 + mg, rB = rA + 8;
            int cw = hd * 8 + nh * 4 + mt;
            uint32_t h, l;
            bfsplit2(acc.x, acc.y, h, l); OP[rA * 50 + cw] = make_uint2(h, l);
            bfsplit2(acc.z, acc.w, h, l); OP[rB * 50 + cw] = make_uint2(h, l);
        }
        __syncthreads();
    }

    // ---- proj + residual -> Y ----
    {
        float4 acc[3];
        #pragma unroll
        for (int j = 0; j < 3; j++) {
            int c = nch * 24 + j * 8 + 2 * mt;
            float b0 = __ldg(&bproj[c]), b1v = __ldg(&bproj[c + 1]);
            acc[j].x = b0; acc[j].y = b1v; acc[j].z = b0; acc[j].w = b1v;
        }
        mma_gemm_pk<3, 6>(acc, OP, 50, m0, WPF, nch * 3, mg, mt, tx);
        #pragma unroll
        for (int j = 0; j < 3; j++) {
            int c = nch * 24 + j * 8 + 2 * mt;
            int cw = c / 2;
            int rA = m0 + mg, rB = rA + 8;
            float xA0, xA1, xB0, xB1;
            bfrec2(XP[rA * 50 + cw], xA0, xA1);
            bfrec2(XP[rB * 50 + cw], xB0, xB1);
            Y[rA * QS + c]     = acc[j].x + xA0;
            Y[rA * QS + c + 1] = acc[j].y + xA1;
            Y[rB * QS + c]     = acc[j].z + xB0;
            Y[rB * QS + c + 1] = acc[j].w + xB1;
        }
    }
    __syncthreads();

    // ---- LayerNorm 1 -> split XP (FFN input) ----
    {
        int row = tid >> 3, l8 = tid & 7;
        float s = 0.f, s2 = 0.f;
        #pragma unroll
        for (int q = 0; q < 3; q++) {
            float4 y = *(const float4*)&Y[row * QS + l8 * 12 + q * 4];
            s += (y.x + y.y) + (y.z + y.w);
            s2 = fmaf(y.x, y.x, fmaf(y.y, y.y, fmaf(y.z, y.z, fmaf(y.w, y.w, s2))));
        }
        #pragma unroll
        for (int o = 4; o > 0; o >>= 1) {
            s  += __shfl_xor_sync(0xffffffffu, s,  o);
            s2 += __shfl_xor_sync(0xffffffffu, s2, o);
        }
        if (l8 == 0) {
            float mean = s * (1.0f / 96.0f);
            float var  = fmaf(-mean, mean, s2 * (1.0f / 96.0f));
            stats[row]      = mean;
            stats[64 + row] = rsqrtf(var + 1e-5f);
        }
    }
    __syncthreads();
    for (int idx = tid; idx < 64 * 48; idx += 512) {
        int t = idx / 48, wd = idx - t * 48;
        float mean = stats[t], rstd = stats[64 + t];
        float y0 = (Y[t * QS + 2 * wd]     - mean) * rstd;
        float y1 = (Y[t * QS + 2 * wd + 1] - mean) * rstd;
        y0 = fmaf(y0, __ldg(&gam1[2 * wd]),     __ldg(&beta1[2 * wd]));
        y1 = fmaf(y1, __ldg(&gam1[2 * wd + 1]), __ldg(&beta1[2 * wd + 1]));
        uint32_t hh, ll;
        bfsplit2(y0, y1, hh, ll);
        XP[t * 50 + wd] = make_uint2(hh, ll);
    }
    __syncthreads();

    // ================= FFN =================
    {
        float4 acc[6];
        #pragma unroll
        for (int j = 0; j < 6; j++) {
            int c = nch * 48 + j * 8 + 2 * mt;
            float v0 = __ldg(&b1[c]), v1 = __ldg(&b1[c + 1]);
            acc[j].x = v0; acc[j].y = v1; acc[j].z = v0; acc[j].w = v1;
        }
        mma_gemm_pk<6, 6>(acc, XP, 50, m0, W1F, nch * 6, mg, mt, tx);
        #pragma unroll
        for (int j = 0; j < 6; j++) {
            int cw = nch * 24 + j * 4 + mt;
            int rA = m0 + mg, rB = rA + 8;
            float g0 = 0.5f * acc[j].x * (1.0f + erff(acc[j].x * 0.70710678118654752f));
            float g1 = 0.5f * acc[j].y * (1.0f + erff(acc[j].y * 0.70710678118654752f));
            float g2 = 0.5f * acc[j].z * (1.0f + erff(acc[j].z * 0.70710678118654752f));
            float g3 = 0.5f * acc[j].w * (1.0f + erff(acc[j].w * 0.70710678118654752f));
            uint32_t h, l;
            bfsplit2(g0, g1, h, l); HP[rA * 98 + cw] = make_uint2(h, l);
            bfsplit2(g2, g3, h, l); HP[rB * 98 + cw] = make_uint2(h, l);
        }
    }
    __syncthreads();

    {
        float4 acc[3];
        #pragma unroll
        for (int j = 0; j < 3; j++) {
            int c = nch * 24 + j * 8 + 2 * mt;
            float v0 = __ldg(&b2[c]), v1 = __ldg(&b2[c + 1]);
            acc[j].x = v0; acc[j].y = v1; acc[j].z = v0; acc[j].w = v1;
        }
        mma_gemm_pk<3, 12>(acc, HP, 98, m0, W2F, nch * 3, mg, mt, tx);
        #pragma unroll
        for (int j = 0; j < 3; j++) {
            int c = nch * 24 + j * 8 + 2 * mt;
            int cw = c / 2;
            int rA = m0 + mg, rB = rA + 8;
            float xA0, xA1, xB0, xB1;
            bfrec2(XP[rA * 50 + cw], xA0, xA1);
            bfrec2(XP[rB * 50 + cw], xB0, xB1);
            Y[rA * QS + c]     = acc[j].x + xA0;
            Y[rA * QS + c + 1] = acc[j].y + xA1;
            Y[rB * QS + c]     = acc[j].z + xB0;
            Y[rB * QS + c + 1] = acc[j].w + xB1;
        }
    }
    __syncthreads();

    // ---- LayerNorm 2 + scatter ----
    {
        int row = tid >> 3, l8 = tid & 7;
        float s = 0.f, s2 = 0.f;
        #pragma unroll
        for (int q = 0; q < 3; q++) {
            float4 y = *(const float4*)&Y[row * QS + l8 * 12 + q * 4];
            s += (y.x + y.y) + (y.z + y.w);
            s2 = fmaf(y.x, y.x, fmaf(y.y, y.y, fmaf(y.z, y.z, fmaf(y.w, y.w, s2))));
        }
        #pragma unroll
        for (int o = 4; o > 0; o >>= 1) {
            s  += __shfl_xor_sync(0xffffffffu, s,  o);
            s2 += __shfl_xor_sync(0xffffffffu, s2, o);
        }
        if (l8 == 0) {
            float mean = s * (1.0f / 96.0f);
            float var  = fmaf(-mean, mean, s2 * (1.0f / 96.0f));
            stats[row]      = mean;
            stats[64 + row] = rsqrtf(var + 1e-5f);
        }
    }
    __syncthreads();

    for (int idx = tid; idx < NTOK * CH; idx += 512) {
        int t = idx / CH, c = idx - t * CH;
        int r = t >> 3, cl = t & 7;
        int h = wr * 8 + r, w = wc * 8 + cl;
        if (SHIFTED) { h += 4; if (h >= HH) h -= HH; w += 4; if (w >= WWI) w -= WWI; }
        float yv = (Y[t * QS + c] - stats[t]) * stats[64 + t];
        dst[(h * WWI + w) * CH + c] = fmaf(yv, gam2[c], beta2[c]);
    }
}

// ---------------------------------------------------------------------------
// Input order (setup_inputs dict order):
//   0: x | 1..7: sa1 | 8..14: sa2 | 15..20: ff1 | 21..26: ff2
// ---------------------------------------------------------------------------
extern "C" void kernel_launch(void* const* d_in, const int* in_sizes, int n_in,
                              void* d_out, int out_size) {
    const float* x = (const float*)d_in[0];
    float *imgA, *imgB, *bias;
    uint4* wf;
    cudaGetSymbolAddress((void**)&imgA, g_imgA);
    cudaGetSymbolAddress((void**)&imgB, g_imgB);
    cudaGetSymbolAddress((void**)&wf,   g_wfrag);
    cudaGetSymbolAddress((void**)&bias, g_bias);

    cudaFuncSetAttribute(block_kernel<0>, cudaFuncAttributeMaxDynamicSharedMemorySize, BLK_SMEM);
    cudaFuncSetAttribute(block_kernel<1>, cudaFuncAttributeMaxDynamicSharedMemorySize, BLK_SMEM);

    split_all_weights<<<dim3(27, 8), 256>>>(
        (const float*)d_in[1],  (const float*)d_in[4],
        (const float*)d_in[8],  (const float*)d_in[11],
        (const float*)d_in[15], (const float*)d_in[21],
        (const float*)d_in[17], (const float*)d_in[23]);

    build_bias<<<dim3(384, 2), 256>>>((const float*)d_in[3], (const float*)d_in[10]);

    dim3 tb(32, 8);
    dim3 tg(HW / 32, CH / 32, BATCH);

    transpose_in_kernel<<<tg, tb>>>(x, imgA);

    block_kernel<0><<<NWIN, 512, BLK_SMEM>>>(
        imgA, imgB, wf + WF_SA1_QKV,
        (const float*)d_in[2], bias,
        wf + WF_SA1_PROJ, (const float*)d_in[5],
        (const float*)d_in[6], (const float*)d_in[7],
        wf + WF_FF1_W1, (const float*)d_in[16],
        wf + WF_FF1_W2, (const float*)d_in[18],
        (const float*)d_in[19], (const float*)d_in[20]);

    block_kernel<1><<<NWIN, 512, BLK_SMEM>>>(
        imgB, imgA, wf + WF_SA2_QKV,
        (const float*)d_in[9], bias + 98304,
        wf + WF_SA2_PROJ, (const float*)d_in[12],
        (const float*)d_in[13], (const float*)d_in[14],
        wf + WF_FF2_W1, (const float*)d_in[22],
        wf + WF_FF2_W2, (const float*)d_in[24],
        (const float*)d_in[25], (const float*)d_in[26]);

    transpose_out_kernel<<<tg, tb>>>(imgA, (float*)d_out);
}

// round 16
// speedup vs baseline: 1.0644x; 1.0644x over previous
#include <cuda_runtime.h>
#include <cuda_bf16.h>
#include <math.h>
#include <stdint.h>

#define CH    96
#define HH    192
#define WWI   192
#define HW    (HH*WWI)        // 36864
#define BATCH 4
#define NWIN_PER 576          // 24*24 windows per image
#define NWIN  (BATCH*NWIN_PER)
#define NTOK  64
#define QS    100             // fp32 row stride (Y)

// 56.6 MB each — static device scratch (no allocations allowed)
__device__ float g_imgA[BATCH*HW*CH];
__device__ float g_imgB[BATCH*HW*CH];

// fragment-packed bf16 weights: per (n_tile, ks) 32 x uint4{bh0,bh1,bl0,bl1}
#define WF_SA1_QKV   0         // 288*96/4 = 6912
#define WF_SA1_PROJ  6912      // 96*96/4  = 2304
#define WF_SA2_QKV   9216
#define WF_SA2_PROJ  16128
#define WF_FF1_W1    18432     // 192*96/4 = 4608
#define WF_FF2_W1    23040
#define WF_FF1_W2    27648     // 96*192/4 = 4608
#define WF_FF2_W2    32256     // -> total 36864
__device__ __align__(16) uint4 g_wfrag[36864];

// fragment-packed bias+mask: [table(2)][variant(4)][head(6)][hm,nh,jt(32)][lane(32)]
// float4 per entry = {b(iA,c), b(iA,c+1), b(iB,c), b(iB,c+1)} ; 49152 float4
__device__ __align__(16) float4 g_bias4[49152];

// ---------------------------------------------------------------------------
__device__ __forceinline__ float fexp(float x) {
    x = fmaxf(x, -80.0f);
    const float L2E = 1.4426950408889634f;
    float t = fmaf(x, L2E, 12582912.0f);
    float n = t - 12582912.0f;
    float f = fmaf(x, L2E, -n);
    float p = 1.5403530393381608e-4f;
    p = fmaf(p, f, 1.3333558146428443e-3f);
    p = fmaf(p, f, 9.6181291076284772e-3f);
    p = fmaf(p, f, 5.5504108664821580e-2f);
    p = fmaf(p, f, 2.4022650695910072e-1f);
    p = fmaf(p, f, 6.9314718055994531e-1f);
    p = fmaf(p, f, 1.0f);
    int e = (int)n;
    float s = __int_as_float((127 + e) << 23);
    return p * s;
}

// ---------------------------------------------------------------------------
// bf16 split/reconstruct + m16n8k16 bf16 MMA (3-term: err ~2^-18)
// ---------------------------------------------------------------------------
__device__ __forceinline__ void bfsplit2(float x0, float x1, uint32_t& h2, uint32_t& l2) {
    uint32_t h;
    asm("cvt.rn.bf16x2.f32 %0, %1, %2;" : "=r"(h) : "f"(x1), "f"(x0));
    float h0 = __uint_as_float(h << 16);
    float h1 = __uint_as_float(h & 0xffff0000u);
    uint32_t l;
    asm("cvt.rn.bf16x2.f32 %0, %1, %2;" : "=r"(l) : "f"(x1 - h1), "f"(x0 - h0));
    h2 = h; l2 = l;
}
__device__ __forceinline__ void bfsplit1(float x, __nv_bfloat16& h, __nv_bfloat16& l) {
    h = __float2bfloat16(x);
    l = __float2bfloat16(x - __bfloat162float(h));
}
__device__ __forceinline__ void bfrec2(uint2 w, float& x0, float& x1) {
    x0 = __uint_as_float(w.x << 16)          + __uint_as_float(w.y << 16);
    x1 = __uint_as_float(w.x & 0xffff0000u)  + __uint_as_float(w.y & 0xffff0000u);
}
__device__ __forceinline__ void mma_bf16(float4& d, const uint32_t* a,
                                         uint32_t b0, uint32_t b1) {
    asm volatile("mma.sync.aligned.m16n8k16.row.col.f32.bf16.bf16.f32 "
                 "{%0,%1,%2,%3},{%4,%5,%6,%7},{%8,%9},{%0,%1,%2,%3};"
                 : "+f"(d.x), "+f"(d.y), "+f"(d.z), "+f"(d.w)
                 : "r"(a[0]), "r"(a[1]), "r"(a[2]), "r"(a[3]), "r"(b0), "r"(b1));
}

// C = A(pre-split interleaved uint2 plane [row][kword], stride ldaw)
//   @ B(fragment-packed uint4).
template<int NT, int KST>
__device__ __forceinline__ void mma_gemm_pk(
    float4* acc, const uint2* A, int ldaw, int m0,
    const uint4* __restrict__ Bf, int nt0, int mg, int mt, int tx)
{
    #pragma unroll
    for (int ks = 0; ks < KST; ks++) {
        uint2 a0 = A[(m0 + mg) * ldaw + ks * 8 + mt];
        uint2 a1 = A[(m0 + mg + 8) * ldaw + ks * 8 + mt];
        uint2 a2 = A[(m0 + mg) * ldaw + ks * 8 + 4 + mt];
        uint2 a3 = A[(m0 + mg + 8) * ldaw + ks * 8 + 4 + mt];
        uint32_t ah[4] = {a0.x, a1.x, a2.x, a3.x};
        uint32_t al[4] = {a0.y, a1.y, a2.y, a3.y};
        #pragma unroll
        for (int j = 0; j < NT; j++) {
            uint4 w = __ldg(&Bf[((nt0 + j) * KST + ks) * 32 + tx]);
            mma_bf16(acc[j], ah, w.x, w.y);
            mma_bf16(acc[j], ah, w.z, w.w);
            mma_bf16(acc[j], al, w.x, w.y);
        }
    }
}

// ---------------------------------------------------------------------------
// Weight prep: W[K][N] fp32 -> fragment-packed uint4 per (n_tile, ks, lane).
// ---------------------------------------------------------------------------
__global__ void split_all_weights(
    const float* s0, const float* s1, const float* s2, const float* s3,
    const float* s4, const float* s5, const float* s6, const float* s7)
{
    const int Ks[8]  = {96, 96, 96, 96, 96, 96, 192, 192};
    const int Ns[8]  = {288, 96, 288, 96, 192, 192, 96, 96};
    const int off[8] = {WF_SA1_QKV, WF_SA1_PROJ, WF_SA2_QKV, WF_SA2_PROJ,
                        WF_FF1_W1, WF_FF2_W1, WF_FF1_W2, WF_FF2_W2};
    int m = blockIdx.y;
    int K = Ks[m], N = Ns[m];
    int KST = K / 16;
    int total = (N / 8) * KST * 32;
    int e = blockIdx.x * 256 + threadIdx.x;
    if (e >= total) return;
    const float* src;
    switch (m) {
        case 0: src = s0; break; case 1: src = s1; break;
        case 2: src = s2; break; case 3: src = s3; break;
        case 4: src = s4; break; case 5: src = s5; break;
        case 6: src = s6; break; default: src = s7; break;
    }
    int lane  = e & 31;
    int ks    = (e >> 5) % KST;
    int ntile = e / (32 * KST);
    int mg = lane >> 2, mt = lane & 3;
    int n  = ntile * 8 + mg;
    int k0 = ks * 16;
    float x0 = src[(k0 + 2 * mt)     * N + n];
    float x1 = src[(k0 + 2 * mt + 1) * N + n];
    float x2 = src[(k0 + 8 + 2 * mt)     * N + n];
    float x3 = src[(k0 + 8 + 2 * mt + 1) * N + n];
    uint32_t bh0, bl0, bh1, bl1;
    bfsplit2(x0, x1, bh0, bl0);
    bfsplit2(x2, x3, bh1, bl1);
    g_wfrag[off[m] + e] = make_uint4(bh0, bh1, bl0, bl1);
}

// ---------------------------------------------------------------------------
// Bias prep: table[T][6] -> fragment-packed float4 with shift mask.
// e (per table) = ((v*6 + hd)*1024) + hm*256 + nh*128 + jt*32 + lane
// ---------------------------------------------------------------------------
__global__ void build_bias(const float* __restrict__ t1, const float* __restrict__ t2) {
    int tb = blockIdx.y;
    int e  = blockIdx.x * 256 + threadIdx.x;   // [0, 24576)
    if (e >= 24576) return;
    const float* tab = tb ? t2 : t1;
    int v  = e / 6144;
    int r  = e - v * 6144;
    int hd = r / 1024;
    int f  = r - hd * 1024;
    int lane = f & 31;
    int jt   = (f >> 5) & 3;
    int nh   = (f >> 7) & 1;
    int hm   = f >> 8;
    int mg = lane >> 2, mt = lane & 3;
    int iA = hm * 16 + mg, iB = iA + 8;
    int c  = nh * 32 + jt * 8 + 2 * mt;
    int wr23 = v & 2, wc23 = v & 1;
    float o[4];
    #pragma unroll
    for (int k = 0; k < 4; k++) {
        int i = (k < 2) ? iA : iB;
        int j = c + (k & 1);
        int ri = i >> 3, ci = i & 7, rj = j >> 3, cj = j & 7;
        float bias = tab[((ri - rj + 7) * 15 + (ci - cj + 7)) * 6 + hd];
        int cnti = (wr23 ? (ri < 4 ? 1 : 2) : 0) * 3 + (wc23 ? (ci < 4 ? 1 : 2) : 0);
        int cntj = (wr23 ? (rj < 4 ? 1 : 2) : 0) * 3 + (wc23 ? (cj < 4 ? 1 : 2) : 0);
        if (cnti != cntj) bias -= 100.f;
        o[k] = bias;
    }
    g_bias4[tb * 24576 + e] = make_float4(o[0], o[1], o[2], o[3]);
}

// ---------------------------------------------------------------------------
// Transposes: [B,C,H,W] <-> [B,HW,C]
// ---------------------------------------------------------------------------
__global__ void transpose_in_kernel(const float* __restrict__ x, float* __restrict__ img) {
    __shared__ float tile[32][33];
    int b = blockIdx.z;
    int hw0 = blockIdx.x * 32, c0 = blockIdx.y * 32;
    const float* src = x + (size_t)b * CH * HW;
    float* dst = img + (size_t)b * HW * CH;
    #pragma unroll
    for (int i = threadIdx.y; i < 32; i += 8)
        tile[i][threadIdx.x] = src[(size_t)(c0 + i) * HW + hw0 + threadIdx.x];
    __syncthreads();
    #pragma unroll
    for (int i = threadIdx.y; i < 32; i += 8)
        dst[(size_t)(hw0 + i) * CH + c0 + threadIdx.x] = tile[threadIdx.x][i];
}

__global__ void transpose_out_kernel(const float* __restrict__ img, float* __restrict__ x) {
    __shared__ float tile[32][33];
    int b = blockIdx.z;
    int hw0 = blockIdx.x * 32, c0 = blockIdx.y * 32;
    const float* src = img + (size_t)b * HW * CH;
    float* dst = x + (size_t)b * CH * HW;
    #pragma unroll
    for (int i = threadIdx.y; i < 32; i += 8)
        tile[i][threadIdx.x] = src[(size_t)(hw0 + i) * CH + c0 + threadIdx.x];
    __syncthreads();
    #pragma unroll
    for (int i = threadIdx.y; i < 32; i += 8)
        dst[(size_t)(c0 + i) * HW + hw0 + threadIdx.x] = tile[threadIdx.x][i];
}

// ---------------------------------------------------------------------------
// Fused Swin block (attention + FFN) per window. bf16 3-term mma everywhere;
// in-register softmax with two-half merge; FRAGMENT-PACKED bias (LDG.128).
// smem (4B words): Y 6400 | stats 128 | ST 512 | XP 6400 | OP 6400 | QP 6400
//   | KP 6400 | SP 8704 | VH 3456 | VL 3456 = 48,256 words = 193,024 B
// FFN: HP (12544 w) overlays QP+KP.
// ---------------------------------------------------------------------------
#define BLK_SMEM 193024

template<int SHIFTED>
__global__ void __launch_bounds__(512, 1) block_kernel(
    const float* __restrict__ in, float* __restrict__ out,
    const uint4* __restrict__ WQF, const float* __restrict__ bqkv,
    const float4* __restrict__ BiasT,
    const uint4* __restrict__ WPF, const float* __restrict__ bproj,
    const float* __restrict__ gam1, const float* __restrict__ beta1,
    const uint4* __restrict__ W1F, const float* __restrict__ b1,
    const uint4* __restrict__ W2F, const float* __restrict__ b2,
    const float* __restrict__ gam2, const float* __restrict__ beta2)
{
    extern __shared__ float sm[];
    float*  Y     = sm;                    // 6400 fp32
    float*  stats = Y + 6400;              // 128
    float2* ST    = (float2*)(stats + 128);// 256 float2 (softmax stats)
    uint2*  XP    = (uint2*)(stats + 128 + 512); // 3200 uint2
    uint2*  OP    = XP + 3200;
    uint2*  QP    = OP + 3200;
    uint2*  KP    = QP + 3200;
    uint2*  SP    = KP + 3200;             // 4352 uint2 (2 x 64 x 34)
    uint32_t* VH  = (uint32_t*)(SP + 4352);// 3456 words
    uint32_t* VL  = VH + 3456;
    __nv_bfloat16* VHs = (__nv_bfloat16*)VH;
    __nv_bfloat16* VLs = (__nv_bfloat16*)VL;
    uint2*  HP    = QP;                    // FFN hidden overlays QP+KP

    const int tid = threadIdx.x;
    const int wid = blockIdx.x;
    const int b  = wid / NWIN_PER;
    const int wl = wid - b * NWIN_PER;
    const int wr = wl / 24, wc = wl - (wl / 24) * 24;
    const float* src = in  + (size_t)b * HW * CH;
    float*       dst = out + (size_t)b * HW * CH;
    const int variant = SHIFTED ? (((wr == 23) ? 2 : 0) | ((wc == 23) ? 1 : 0)) : 0;
    const float4* BiasV = BiasT + variant * 6144;

    // ---- gather window tokens into split plane XP ----
    for (int idx = tid; idx < 64 * 48; idx += 512) {
        int t = idx / 48, wd = idx - t * 48;
        int r = t >> 3, cl = t & 7;
        int h = wr * 8 + r, w = wc * 8 + cl;
        if (SHIFTED) { h += 4; if (h >= HH) h -= HH; w += 4; if (w >= WWI) w -= WWI; }
        float2 v = *(const float2*)&src[(h * WWI + w) * CH + 2 * wd];
        uint32_t hh, ll;
        bfsplit2(v.x, v.y, hh, ll);
        XP[t * 50 + wd] = make_uint2(hh, ll);
    }
    __syncthreads();

    const int wg = tid >> 5, tx = tid & 31;   // 16 warps
    const int mg = tx >> 2, mt = tx & 3;
    const int m0 = (wg & 3) * 16;
    const int nch = wg >> 2;

    // ================= ATTENTION =================
    // ---- QKV GEMM -> split Q/K planes + transposed V planes ----
    {
        float4 acc[9];
        #pragma unroll
        for (int j = 0; j < 9; j++) {
            int c = nch * 72 + j * 8 + 2 * mt;
            float b0 = __ldg(&bqkv[c]), b1v = __ldg(&bqkv[c + 1]);
            acc[j].x = b0; acc[j].y = b1v; acc[j].z = b0; acc[j].w = b1v;
        }
        mma_gemm_pk<9, 6>(acc, XP, 50, m0, WQF, nch * 9, mg, mt, tx);
        #pragma unroll
        for (int j = 0; j < 9; j++) {
            int cb = nch * 72 + j * 8;
            int c  = cb + 2 * mt;
            int rA = m0 + mg, rB = rA + 8;
            if (cb < 96) {
                int cw = c / 2;
                uint32_t h, l;
                bfsplit2(acc[j].x, acc[j].y, h, l); QP[rA * 50 + cw] = make_uint2(h, l);
                bfsplit2(acc[j].z, acc[j].w, h, l); QP[rB * 50 + cw] = make_uint2(h, l);
            } else if (cb < 192) {
                int cw = (c - 96) / 2;
                uint32_t h, l;
                bfsplit2(acc[j].x, acc[j].y, h, l); KP[rA * 50 + cw] = make_uint2(h, l);
                bfsplit2(acc[j].z, acc[j].w, h, l); KP[rB * 50 + cw] = make_uint2(h, l);
            } else {
                int d = c - 192;
                __nv_bfloat16 h, l;
                bfsplit1(acc[j].x, h, l); VHs[d * 72 + rA] = h;       VLs[d * 72 + rA] = l;
                bfsplit1(acc[j].y, h, l); VHs[(d + 1) * 72 + rA] = h; VLs[(d + 1) * 72 + rA] = l;
                bfsplit1(acc[j].z, h, l); VHs[d * 72 + rB] = h;       VLs[d * 72 + rB] = l;
                bfsplit1(acc[j].w, h, l); VHs[(d + 1) * 72 + rB] = h; VLs[(d + 1) * 72 + rB] = l;
            }
        }
    }
    __syncthreads();

    // ---- heads: 2 in flight; 8 warps/head; in-register softmax ----
    const int hg = wg >> 3;
    const int w8 = wg & 7;
    const int hm = w8 & 3;
    const int nh = w8 >> 2;

    for (int it = 0; it < 3; it++) {
        const int hd = it * 2 + hg;
        uint2* SPg = SP + hg * (64 * 34);

        // scores + fragment-packed bias + in-register softmax -> split SP
        {
            float4 acc[4];
            #pragma unroll
            for (int jt = 0; jt < 4; jt++) acc[jt] = make_float4(0.f, 0.f, 0.f, 0.f);
            int qw = (hm * 16 + mg) * 50 + hd * 8 + mt;
            uint2 q0 = QP[qw], q1 = QP[qw + 400], q2 = QP[qw + 4], q3 = QP[qw + 404];
            uint32_t ah[4] = {q0.x, q1.x, q2.x, q3.x};
            uint32_t al[4] = {q0.y, q1.y, q2.y, q3.y};
            #pragma unroll
            for (int jt = 0; jt < 4; jt++) {
                int kw = (nh * 32 + jt * 8 + mg) * 50 + hd * 8 + mt;
                uint2 b0 = KP[kw], b1v = KP[kw + 4];
                mma_bf16(acc[jt], ah, b0.x, b1v.x);
                mma_bf16(acc[jt], ah, b0.y, b1v.y);
                mma_bf16(acc[jt], al, b0.x, b1v.x);
            }
            const int iA = hm * 16 + mg, iB = iA + 8;
            const float4* BP4 = BiasV + hd * 1024 + (hm * 2 + nh) * 128;
            float mA = -1e30f, mB = -1e30f;
            #pragma unroll
            for (int jt = 0; jt < 4; jt++) {
                float4 bf = __ldg(&BP4[jt * 32 + tx]);
                acc[jt].x = fmaf(acc[jt].x, 0.25f, bf.x);
                acc[jt].y = fmaf(acc[jt].y, 0.25f, bf.y);
                acc[jt].z = fmaf(acc[jt].z, 0.25f, bf.z);
                acc[jt].w = fmaf(acc[jt].w, 0.25f, bf.w);
                mA = fmaxf(mA, fmaxf(acc[jt].x, acc[jt].y));
                mB = fmaxf(mB, fmaxf(acc[jt].z, acc[jt].w));
            }
            // reduce over mt lanes (lane = mg*4+mt)
            mA = fmaxf(mA, __shfl_xor_sync(0xffffffffu, mA, 1));
            mA = fmaxf(mA, __shfl_xor_sync(0xffffffffu, mA, 2));
            mB = fmaxf(mB, __shfl_xor_sync(0xffffffffu, mB, 1));
            mB = fmaxf(mB, __shfl_xor_sync(0xffffffffu, mB, 2));
            float sA = 0.f, sB = 0.f;
            #pragma unroll
            for (int jt = 0; jt < 4; jt++) {
                acc[jt].x = fexp(acc[jt].x - mA); acc[jt].y = fexp(acc[jt].y - mA);
                acc[jt].z = fexp(acc[jt].z - mB); acc[jt].w = fexp(acc[jt].w - mB);
                sA += acc[jt].x + acc[jt].y;
                sB += acc[jt].z + acc[jt].w;
            }
            sA += __shfl_xor_sync(0xffffffffu, sA, 1);
            sA += __shfl_xor_sync(0xffffffffu, sA, 2);
            sB += __shfl_xor_sync(0xffffffffu, sB, 1);
            sB += __shfl_xor_sync(0xffffffffu, sB, 2);
            if (mt == 0) {
                ST[((hg * 64 + iA) << 1) | nh] = make_float2(mA, sA);
                ST[((hg * 64 + iB) << 1) | nh] = make_float2(mB, sB);
            }
            __syncthreads();
            // merge two halves per row, compute local scale
            float2 pA0 = ST[(hg * 64 + iA) << 1], pA1 = ST[((hg * 64 + iA) << 1) | 1];
            float2 pB0 = ST[(hg * 64 + iB) << 1], pB1 = ST[((hg * 64 + iB) << 1) | 1];
            float MA = fmaxf(pA0.x, pA1.x);
            float SAt = pA0.y * fexp(pA0.x - MA) + pA1.y * fexp(pA1.x - MA);
            float scaleA = fexp(mA - MA) / SAt;
            float MB = fmaxf(pB0.x, pB1.x);
            float SBt = pB0.y * fexp(pB0.x - MB) + pB1.y * fexp(pB1.x - MB);
            float scaleB = fexp(mB - MB) / SBt;
            #pragma unroll
            for (int jt = 0; jt < 4; jt++) {
                int kw = nh * 16 + jt * 4 + mt;
                uint32_t h, l;
                bfsplit2(acc[jt].x * scaleA, acc[jt].y * scaleA, h, l);
                SPg[iA * 34 + kw] = make_uint2(h, l);
                bfsplit2(acc[jt].z * scaleB, acc[jt].w * scaleB, h, l);
                SPg[iB * 34 + kw] = make_uint2(h, l);
            }
        }
        __syncthreads();

        // AV -> split OP
        {
            int nc0 = hd * 16 + nh * 8;
            float4 acc = make_float4(0.f, 0.f, 0.f, 0.f);
            #pragma unroll
            for (int ks = 0; ks < 4; ks++) {
                int spw = (hm * 16 + mg) * 34 + ks * 8 + mt;
                uint2 a0 = SPg[spw],     a1 = SPg[spw + 272];
                uint2 a2 = SPg[spw + 4], a3 = SPg[spw + 276];
                uint32_t ah[4] = {a0.x, a1.x, a2.x, a3.x};
                uint32_t al[4] = {a0.y, a1.y, a2.y, a3.y};
                int vw = (nc0 + mg) * 36 + ks * 8 + mt;
                uint32_t bh0 = VH[vw], bh1 = VH[vw + 4];
                uint32_t bl0 = VL[vw], bl1 = VL[vw + 4];
                mma_bf16(acc, ah, bh0, bh1);
                mma_bf16(acc, ah, bl0, bl1);
                mma_bf16(acc, al, bh0, bh1);
            }
            int rA = hm * 16 + mg, rB = rA + 8;
            int cw = hd * 8 + nh * 4 + mt;
            uint32_t h, l;
            bfsplit2(acc.x, acc.y, h, l); OP[rA * 50 + cw] = make_uint2(h, l);
            bfsplit2(acc.z, acc.w, h, l); OP[rB * 50 + cw] = make_uint2(h, l);
        }
        __syncthreads();
    }

    // ---- proj + residual -> Y ----
    {
        float4 acc[3];
        #pragma unroll
        for (int j = 0; j < 3; j++) {
            int c = nch * 24 + j * 8 + 2 * mt;
            float b0 = __ldg(&bproj[c]), b1v = __ldg(&bproj[c + 1]);
            acc[j].x = b0; acc[j].y = b1v; acc[j].z = b0; acc[j].w = b1v;
        }
        mma_gemm_pk<3, 6>(acc, OP, 50, m0, WPF, nch * 3, mg, mt, tx);
        #pragma unroll
        for (int j = 0; j < 3; j++) {
            int c = nch * 24 + j * 8 + 2 * mt;
            int cw = c / 2;
            int rA = m0 + mg, rB = rA + 8;
            float xA0, xA1, xB0, xB1;
            bfrec2(XP[rA * 50 + cw], xA0, xA1);
            bfrec2(XP[rB * 50 + cw], xB0, xB1);
            Y[rA * QS + c]     = acc[j].x + xA0;
            Y[rA * QS + c + 1] = acc[j].y + xA1;
            Y[rB * QS + c]     = acc[j].z + xB0;
            Y[rB * QS + c + 1] = acc[j].w + xB1;
        }
    }
    __syncthreads();

    // ---- LayerNorm 1 -> split XP (FFN input) ----
    {
        int row = tid >> 3, l8 = tid & 7;
        float s = 0.f, s2 = 0.f;
        #pragma unroll
        for (int q = 0; q < 3; q++) {
            float4 y = *(const float4*)&Y[row * QS + l8 * 12 + q * 4];
            s += (y.x + y.y) + (y.z + y.w);
            s2 = fmaf(y.x, y.x, fmaf(y.y, y.y, fmaf(y.z, y.z, fmaf(y.w, y.w, s2))));
        }
        #pragma unroll
        for (int o = 4; o > 0; o >>= 1) {
            s  += __shfl_xor_sync(0xffffffffu, s,  o);
            s2 += __shfl_xor_sync(0xffffffffu, s2, o);
        }
        if (l8 == 0) {
            float mean = s * (1.0f / 96.0f);
            float var  = fmaf(-mean, mean, s2 * (1.0f / 96.0f));
            stats[row]      = mean;
            stats[64 + row] = rsqrtf(var + 1e-5f);
        }
    }
    __syncthreads();
    for (int idx = tid; idx < 64 * 48; idx += 512) {
        int t = idx / 48, wd = idx - t * 48;
        float mean = stats[t], rstd = stats[64 + t];
        float y0 = (Y[t * QS + 2 * wd]     - mean) * rstd;
        float y1 = (Y[t * QS + 2 * wd + 1] - mean) * rstd;
        y0 = fmaf(y0, __ldg(&gam1[2 * wd]),     __ldg(&beta1[2 * wd]));
        y1 = fmaf(y1, __ldg(&gam1[2 * wd + 1]), __ldg(&beta1[2 * wd + 1]));
        uint32_t hh, ll;
        bfsplit2(y0, y1, hh, ll);
        XP[t * 50 + wd] = make_uint2(hh, ll);
    }
    __syncthreads();

    // ================= FFN =================
    {
        float4 acc[6];
        #pragma unroll
        for (int j = 0; j < 6; j++) {
            int c = nch * 48 + j * 8 + 2 * mt;
            float v0 = __ldg(&b1[c]), v1 = __ldg(&b1[c + 1]);
            acc[j].x = v0; acc[j].y = v1; acc[j].z = v0; acc[j].w = v1;
        }
        mma_gemm_pk<6, 6>(acc, XP, 50, m0, W1F, nch * 6, mg, mt, tx);
        #pragma unroll
        for (int j = 0; j < 6; j++) {
            int cw = nch * 24 + j * 4 + mt;
            int rA = m0 + mg, rB = rA + 8;
            float g0 = 0.5f * acc[j].x * (1.0f + erff(acc[j].x * 0.70710678118654752f));
            float g1 = 0.5f * acc[j].y * (1.0f + erff(acc[j].y * 0.70710678118654752f));
            float g2 = 0.5f * acc[j].z * (1.0f + erff(acc[j].z * 0.70710678118654752f));
            float g3 = 0.5f * acc[j].w * (1.0f + erff(acc[j].w * 0.70710678118654752f));
            uint32_t h, l;
            bfsplit2(g0, g1, h, l); HP[rA * 98 + cw] = make_uint2(h, l);
            bfsplit2(g2, g3, h, l); HP[rB * 98 + cw] = make_uint2(h, l);
        }
    }
    __syncthreads();

    {
        float4 acc[3];
        #pragma unroll
        for (int j = 0; j < 3; j++) {
            int c = nch * 24 + j * 8 + 2 * mt;
            float v0 = __ldg(&b2[c]), v1 = __ldg(&b2[c + 1]);
            acc[j].x = v0; acc[j].y = v1; acc[j].z = v0; acc[j].w = v1;
        }
        mma_gemm_pk<3, 12>(acc, HP, 98, m0, W2F, nch * 3, mg, mt, tx);
        #pragma unroll
        for (int j = 0; j < 3; j++) {
            int c = nch * 24 + j * 8 + 2 * mt;
            int cw = c / 2;
            int rA = m0 + mg, rB = rA + 8;
            float xA0, xA1, xB0, xB1;
            bfrec2(XP[rA * 50 + cw], xA0, xA1);
            bfrec2(XP[rB * 50 + cw], xB0, xB1);
            Y[rA * QS + c]     = acc[j].x + xA0;
            Y[rA * QS + c + 1] = acc[j].y + xA1;
            Y[rB * QS + c]     = acc[j].z + xB0;
            Y[rB * QS + c + 1] = acc[j].w + xB1;
        }
    }
    __syncthreads();

    // ---- LayerNorm 2 + scatter ----
    {
        int row = tid >> 3, l8 = tid & 7;
        float s = 0.f, s2 = 0.f;
        #pragma unroll
        for (int q = 0; q < 3; q++) {
            float4 y = *(const float4*)&Y[row * QS + l8 * 12 + q * 4];
            s += (y.x + y.y) + (y.z + y.w);
            s2 = fmaf(y.x, y.x, fmaf(y.y, y.y, fmaf(y.z, y.z, fmaf(y.w, y.w, s2))));
        }
        #pragma unroll
        for (int o = 4; o > 0; o >>= 1) {
            s  += __shfl_xor_sync(0xffffffffu, s,  o);
            s2 += __shfl_xor_sync(0xffffffffu, s2, o);
        }
        if (l8 == 0) {
            float mean = s * (1.0f / 96.0f);
            float var  = fmaf(-mean, mean, s2 * (1.0f / 96.0f));
            stats[row]      = mean;
            stats[64 + row] = rsqrtf(var + 1e-5f);
        }
    }
    __syncthreads();

    for (int idx = tid; idx < NTOK * CH; idx += 512) {
        int t = idx / CH, c = idx - t * CH;
        int r = t >> 3, cl = t & 7;
        int h = wr * 8 + r, w = wc * 8 + cl;
        if (SHIFTED) { h += 4; if (h >= HH) h -= HH; w += 4; if (w >= WWI) w -= WWI; }
        float yv = (Y[t * QS + c] - stats[t]) * stats[64 + t];
        dst[(h * WWI + w) * CH + c] = fmaf(yv, gam2[c], beta2[c]);
    }
}

// ---------------------------------------------------------------------------
// Input order (setup_inputs dict order):
//   0: x | 1..7: sa1 | 8..14: sa2 | 15..20: ff1 | 21..26: ff2
// ---------------------------------------------------------------------------
extern "C" void kernel_launch(void* const* d_in, const int* in_sizes, int n_in,
                              void* d_out, int out_size) {
    const float* x = (const float*)d_in[0];
    float *imgA, *imgB;
    uint4* wf;
    float4* bias;
    cudaGetSymbolAddress((void**)&imgA, g_imgA);
    cudaGetSymbolAddress((void**)&imgB, g_imgB);
    cudaGetSymbolAddress((void**)&wf,   g_wfrag);
    cudaGetSymbolAddress((void**)&bias, g_bias4);

    cudaFuncSetAttribute(block_kernel<0>, cudaFuncAttributeMaxDynamicSharedMemorySize, BLK_SMEM);
    cudaFuncSetAttribute(block_kernel<1>, cudaFuncAttributeMaxDynamicSharedMemorySize, BLK_SMEM);

    split_all_weights<<<dim3(27, 8), 256>>>(
        (const float*)d_in[1],  (const float*)d_in[4],
        (const float*)d_in[8],  (const float*)d_in[11],
        (const float*)d_in[15], (const float*)d_in[21],
        (const float*)d_in[17], (const float*)d_in[23]);

    build_bias<<<dim3(96, 2), 256>>>((const float*)d_in[3], (const float*)d_in[10]);

    dim3 tb(32, 8);
    dim3 tg(HW / 32, CH / 32, BATCH);

    transpose_in_kernel<<<tg, tb>>>(x, imgA);

    block_kernel<0><<<NWIN, 512, BLK_SMEM>>>(
        imgA, imgB, wf + WF_SA1_QKV,
        (const float*)d_in[2], bias,
        wf + WF_SA1_PROJ, (const float*)d_in[5],
        (const float*)d_in[6], (const float*)d_in[7],
        wf + WF_FF1_W1, (const float*)d_in[16],
        wf + WF_FF1_W2, (const float*)d_in[18],
        (const float*)d_in[19], (const float*)d_in[20]);

    block_kernel<1><<<NWIN, 512, BLK_SMEM>>>(
        imgB, imgA, wf + WF_SA2_QKV,
        (const float*)d_in[9], bias + 24576,
        wf + WF_SA2_PROJ, (const float*)d_in[12],
        (const float*)d_in[13], (const float*)d_in[14],
        wf + WF_FF2_W1, (const float*)d_in[22],
        wf + WF_FF2_W2, (const float*)d_in[24],
        (const float*)d_in[25], (const float*)d_in[26]);

    transpose_out_kernel<<<tg, tb>>>(imgA, (float*)d_out);
}

// round 17
// speedup vs baseline: 1.0906x; 1.0247x over previous
#include <cuda_runtime.h>
#include <cuda_bf16.h>
#include <math.h>
#include <stdint.h>

#define CH    96
#define HH    192
#define WWI   192
#define HW    (HH*WWI)        // 36864
#define BATCH 4
#define NWIN_PER 576          // 24*24 windows per image
#define NWIN  (BATCH*NWIN_PER)
#define NTOK  64
#define QS    100             // fp32 row stride (Y)

// intermediate images in SPLIT-PLANE format: uint2{bf16x2 hi, bf16x2 lo} per
// 2 channels -> 48 words/token. Same byte size as fp32.
__device__ uint2 g_imgA[BATCH*HW*48];
__device__ uint2 g_imgB[BATCH*HW*48];

// fragment-packed bf16 weights: per (n_tile, ks) 32 x uint4{bh0,bh1,bl0,bl1}
#define WF_SA1_QKV   0         // 288*96/4 = 6912
#define WF_SA1_PROJ  6912      // 96*96/4  = 2304
#define WF_SA2_QKV   9216
#define WF_SA2_PROJ  16128
#define WF_FF1_W1    18432     // 192*96/4 = 4608
#define WF_FF2_W1    23040
#define WF_FF1_W2    27648     // 96*192/4 = 4608
#define WF_FF2_W2    32256     // -> total 36864
__device__ __align__(16) uint4 g_wfrag[36864];

// fragment-packed bias+mask: [table(2)][variant(4)][head(6)][hm,nh,jt(32)][lane(32)]
__device__ __align__(16) float4 g_bias4[49152];

// ---------------------------------------------------------------------------
__device__ __forceinline__ float fexp(float x) {
    x = fmaxf(x, -80.0f);
    const float L2E = 1.4426950408889634f;
    float t = fmaf(x, L2E, 12582912.0f);
    float n = t - 12582912.0f;
    float f = fmaf(x, L2E, -n);
    float p = 1.5403530393381608e-4f;
    p = fmaf(p, f, 1.3333558146428443e-3f);
    p = fmaf(p, f, 9.6181291076284772e-3f);
    p = fmaf(p, f, 5.5504108664821580e-2f);
    p = fmaf(p, f, 2.4022650695910072e-1f);
    p = fmaf(p, f, 6.9314718055994531e-1f);
    p = fmaf(p, f, 1.0f);
    int e = (int)n;
    float s = __int_as_float((127 + e) << 23);
    return p * s;
}

// ---------------------------------------------------------------------------
// bf16 split/reconstruct + m16n8k16 bf16 MMA (3-term: err ~2^-18)
// ---------------------------------------------------------------------------
__device__ __forceinline__ void bfsplit2(float x0, float x1, uint32_t& h2, uint32_t& l2) {
    uint32_t h;
    asm("cvt.rn.bf16x2.f32 %0, %1, %2;" : "=r"(h) : "f"(x1), "f"(x0));
    float h0 = __uint_as_float(h << 16);
    float h1 = __uint_as_float(h & 0xffff0000u);
    uint32_t l;
    asm("cvt.rn.bf16x2.f32 %0, %1, %2;" : "=r"(l) : "f"(x1 - h1), "f"(x0 - h0));
    h2 = h; l2 = l;
}
__device__ __forceinline__ void bfsplit1(float x, __nv_bfloat16& h, __nv_bfloat16& l) {
    h = __float2bfloat16(x);
    l = __float2bfloat16(x - __bfloat162float(h));
}
__device__ __forceinline__ void bfrec2(uint2 w, float& x0, float& x1) {
    x0 = __uint_as_float(w.x << 16)          + __uint_as_float(w.y << 16);
    x1 = __uint_as_float(w.x & 0xffff0000u)  + __uint_as_float(w.y & 0xffff0000u);
}
__device__ __forceinline__ void mma_bf16(float4& d, const uint32_t* a,
                                         uint32_t b0, uint32_t b1) {
    asm volatile("mma.sync.aligned.m16n8k16.row.col.f32.bf16.bf16.f32 "
                 "{%0,%1,%2,%3},{%4,%5,%6,%7},{%8,%9},{%0,%1,%2,%3};"
                 : "+f"(d.x), "+f"(d.y), "+f"(d.z), "+f"(d.w)
                 : "r"(a[0]), "r"(a[1]), "r"(a[2]), "r"(a[3]), "r"(b0), "r"(b1));
}

// C = A(pre-split interleaved uint2 plane [row][kword], stride ldaw)
//   @ B(fragment-packed uint4).
template<int NT, int KST>
__device__ __forceinline__ void mma_gemm_pk(
    float4* acc, const uint2* A, int ldaw, int m0,
    const uint4* __restrict__ Bf, int nt0, int mg, int mt, int tx)
{
    #pragma unroll
    for (int ks = 0; ks < KST; ks++) {
        uint2 a0 = A[(m0 + mg) * ldaw + ks * 8 + mt];
        uint2 a1 = A[(m0 + mg + 8) * ldaw + ks * 8 + mt];
        uint2 a2 = A[(m0 + mg) * ldaw + ks * 8 + 4 + mt];
        uint2 a3 = A[(m0 + mg + 8) * ldaw + ks * 8 + 4 + mt];
        uint32_t ah[4] = {a0.x, a1.x, a2.x, a3.x};
        uint32_t al[4] = {a0.y, a1.y, a2.y, a3.y};
        #pragma unroll
        for (int j = 0; j < NT; j++) {
            uint4 w = __ldg(&Bf[((nt0 + j) * KST + ks) * 32 + tx]);
            mma_bf16(acc[j], ah, w.x, w.y);
            mma_bf16(acc[j], ah, w.z, w.w);
            mma_bf16(acc[j], al, w.x, w.y);
        }
    }
}

// ---------------------------------------------------------------------------
// Weight prep: W[K][N] fp32 -> fragment-packed uint4 per (n_tile, ks, lane).
// ---------------------------------------------------------------------------
__global__ void split_all_weights(
    const float* s0, const float* s1, const float* s2, const float* s3,
    const float* s4, const float* s5, const float* s6, const float* s7)
{
    const int Ks[8]  = {96, 96, 96, 96, 96, 96, 192, 192};
    const int Ns[8]  = {288, 96, 288, 96, 192, 192, 96, 96};
    const int off[8] = {WF_SA1_QKV, WF_SA1_PROJ, WF_SA2_QKV, WF_SA2_PROJ,
                        WF_FF1_W1, WF_FF2_W1, WF_FF1_W2, WF_FF2_W2};
    int m = blockIdx.y;
    int K = Ks[m], N = Ns[m];
    int KST = K / 16;
    int total = (N / 8) * KST * 32;
    int e = blockIdx.x * 256 + threadIdx.x;
    if (e >= total) return;
    const float* src;
    switch (m) {
        case 0: src = s0; break; case 1: src = s1; break;
        case 2: src = s2; break; case 3: src = s3; break;
        case 4: src = s4; break; case 5: src = s5; break;
        case 6: src = s6; break; default: src = s7; break;
    }
    int lane  = e & 31;
    int ks    = (e >> 5) % KST;
    int ntile = e / (32 * KST);
    int mg = lane >> 2, mt = lane & 3;
    int n  = ntile * 8 + mg;
    int k0 = ks * 16;
    float x0 = src[(k0 + 2 * mt)     * N + n];
    float x1 = src[(k0 + 2 * mt + 1) * N + n];
    float x2 = src[(k0 + 8 + 2 * mt)     * N + n];
    float x3 = src[(k0 + 8 + 2 * mt + 1) * N + n];
    uint32_t bh0, bl0, bh1, bl1;
    bfsplit2(x0, x1, bh0, bl0);
    bfsplit2(x2, x3, bh1, bl1);
    g_wfrag[off[m] + e] = make_uint4(bh0, bh1, bl0, bl1);
}

// ---------------------------------------------------------------------------
// Bias prep: table[T][6] -> fragment-packed float4 with shift mask.
// ---------------------------------------------------------------------------
__global__ void build_bias(const float* __restrict__ t1, const float* __restrict__ t2) {
    int tb = blockIdx.y;
    int e  = blockIdx.x * 256 + threadIdx.x;   // [0, 24576)
    if (e >= 24576) return;
    const float* tab = tb ? t2 : t1;
    int v  = e / 6144;
    int r  = e - v * 6144;
    int hd = r / 1024;
    int f  = r - hd * 1024;
    int lane = f & 31;
    int jt   = (f >> 5) & 3;
    int nh   = (f >> 7) & 1;
    int hm   = f >> 8;
    int mg = lane >> 2, mt = lane & 3;
    int iA = hm * 16 + mg, iB = iA + 8;
    int c  = nh * 32 + jt * 8 + 2 * mt;
    int wr23 = v & 2, wc23 = v & 1;
    float o[4];
    #pragma unroll
    for (int k = 0; k < 4; k++) {
        int i = (k < 2) ? iA : iB;
        int j = c + (k & 1);
        int ri = i >> 3, ci = i & 7, rj = j >> 3, cj = j & 7;
        float bias = tab[((ri - rj + 7) * 15 + (ci - cj + 7)) * 6 + hd];
        int cnti = (wr23 ? (ri < 4 ? 1 : 2) : 0) * 3 + (wc23 ? (ci < 4 ? 1 : 2) : 0);
        int cntj = (wr23 ? (rj < 4 ? 1 : 2) : 0) * 3 + (wc23 ? (cj < 4 ? 1 : 2) : 0);
        if (cnti != cntj) bias -= 100.f;
        o[k] = bias;
    }
    g_bias4[tb * 24576 + e] = make_float4(o[0], o[1], o[2], o[3]);
}

// ---------------------------------------------------------------------------
// Transposes: fp32 [B,C,H,W] <-> split-plane [B,HW,48] uint2
// ---------------------------------------------------------------------------
__global__ void transpose_in_kernel(const float* __restrict__ x, uint2* __restrict__ img) {
    __shared__ float tile[32][33];
    int b = blockIdx.z;
    int hw0 = blockIdx.x * 32, c0 = blockIdx.y * 32;
    const float* src = x + (size_t)b * CH * HW;
    uint2* dst = img + (size_t)b * HW * 48;
    #pragma unroll
    for (int i = threadIdx.y; i < 32; i += 8)
        tile[i][threadIdx.x] = src[(size_t)(c0 + i) * HW + hw0 + threadIdx.x];
    __syncthreads();
    int t = threadIdx.y * 32 + threadIdx.x;
    for (int e = t; e < 32 * 16; e += 256) {
        int hw = e >> 4, wd = e & 15;
        float v0 = tile[2 * wd][hw], v1 = tile[2 * wd + 1][hw];
        uint32_t hh, ll;
        bfsplit2(v0, v1, hh, ll);
        dst[(size_t)(hw0 + hw) * 48 + (c0 >> 1) + wd] = make_uint2(hh, ll);
    }
}

__global__ void transpose_out_kernel(const uint2* __restrict__ img, float* __restrict__ xo) {
    __shared__ float tile[32][33];
    int b = blockIdx.z;
    int hw0 = blockIdx.x * 32, c0 = blockIdx.y * 32;
    const uint2* src = img + (size_t)b * HW * 48;
    float* dst = xo + (size_t)b * CH * HW;
    int t = threadIdx.y * 32 + threadIdx.x;
    for (int e = t; e < 32 * 16; e += 256) {
        int hw = e >> 4, wd = e & 15;
        uint2 w = src[(size_t)(hw0 + hw) * 48 + (c0 >> 1) + wd];
        float v0, v1;
        bfrec2(w, v0, v1);
        tile[2 * wd][hw]     = v0;
        tile[2 * wd + 1][hw] = v1;
    }
    __syncthreads();
    #pragma unroll
    for (int i = threadIdx.y; i < 32; i += 8)
        dst[(size_t)(c0 + i) * HW + hw0 + threadIdx.x] = tile[i][threadIdx.x];
}

// ---------------------------------------------------------------------------
// Fused Swin block per window. bf16 3-term mma; fragment-packed bias;
// deferred-normalization softmax (unnormalized exp in SP, (m,s) in ST;
// AV applies per-half scales after its sync). Heads loop: 6 syncs (was 9).
// smem (4B words): Y 6400 | stats 128 | ST 512 | XP 6400 | OP 6400 | QP 6400
//   | KP 6400 | SP 8704 | VH 3456 | VL 3456 = 48,256 words = 193,024 B
// ---------------------------------------------------------------------------
#define BLK_SMEM 193024

template<int SHIFTED>
__global__ void __launch_bounds__(512, 1) block_kernel(
    const uint2* __restrict__ in, uint2* __restrict__ out,
    const uint4* __restrict__ WQF, const float* __restrict__ bqkv,
    const float4* __restrict__ BiasT,
    const uint4* __restrict__ WPF, const float* __restrict__ bproj,
    const float* __restrict__ gam1, const float* __restrict__ beta1,
    const uint4* __restrict__ W1F, const float* __restrict__ b1,
    const uint4* __restrict__ W2F, const float* __restrict__ b2,
    const float* __restrict__ gam2, const float* __restrict__ beta2)
{
    extern __shared__ float sm[];
    float*  Y     = sm;                    // 6400 fp32
    float*  stats = Y + 6400;              // 128
    float2* ST    = (float2*)(stats + 128);// 256 float2 (m,s per row-half)
    uint2*  XP    = (uint2*)(stats + 128 + 512);
    uint2*  OP    = XP + 3200;
    uint2*  QP    = OP + 3200;
    uint2*  KP    = QP + 3200;
    uint2*  SP    = KP + 3200;             // 4352 uint2 (2 x 64 x 34)
    uint32_t* VH  = (uint32_t*)(SP + 4352);// 3456 words
    uint32_t* VL  = VH + 3456;
    __nv_bfloat16* VHs = (__nv_bfloat16*)VH;
    __nv_bfloat16* VLs = (__nv_bfloat16*)VL;
    uint2*  HP    = QP;                    // FFN hidden overlays QP+KP

    const int tid = threadIdx.x;
    const int wid = blockIdx.x;
    const int b  = wid / NWIN_PER;
    const int wl = wid - b * NWIN_PER;
    const int wr = wl / 24, wc = wl - (wl / 24) * 24;
    const uint2* src = in  + (size_t)b * HW * 48;
    uint2*       dst = out + (size_t)b * HW * 48;
    const int variant = SHIFTED ? (((wr == 23) ? 2 : 0) | ((wc == 23) ? 1 : 0)) : 0;
    const float4* BiasV = BiasT + variant * 6144;

    // ---- gather window tokens (already split): pure copy ----
    for (int idx = tid; idx < 64 * 48; idx += 512) {
        int t = idx / 48, wd = idx - t * 48;
        int r = t >> 3, cl = t & 7;
        int h = wr * 8 + r, w = wc * 8 + cl;
        if (SHIFTED) { h += 4; if (h >= HH) h -= HH; w += 4; if (w >= WWI) w -= WWI; }
        XP[t * 50 + wd] = src[(size_t)(h * WWI + w) * 48 + wd];
    }
    __syncthreads();

    const int wg = tid >> 5, tx = tid & 31;   // 16 warps
    const int mg = tx >> 2, mt = tx & 3;
    const int m0 = (wg & 3) * 16;
    const int nch = wg >> 2;

    // ================= ATTENTION =================
    // ---- QKV GEMM -> split Q/K planes + transposed V planes ----
    {
        float4 acc[9];
        #pragma unroll
        for (int j = 0; j < 9; j++) {
            int c = nch * 72 + j * 8 + 2 * mt;
            float b0 = __ldg(&bqkv[c]), b1v = __ldg(&bqkv[c + 1]);
            acc[j].x = b0; acc[j].y = b1v; acc[j].z = b0; acc[j].w = b1v;
        }
        mma_gemm_pk<9, 6>(acc, XP, 50, m0, WQF, nch * 9, mg, mt, tx);
        #pragma unroll
        for (int j = 0; j < 9; j++) {
            int cb = nch * 72 + j * 8;
            int c  = cb + 2 * mt;
            int rA = m0 + mg, rB = rA + 8;
            if (cb < 96) {
                int cw = c / 2;
                uint32_t h, l;
                bfsplit2(acc[j].x, acc[j].y, h, l); QP[rA * 50 + cw] = make_uint2(h, l);
                bfsplit2(acc[j].z, acc[j].w, h, l); QP[rB * 50 + cw] = make_uint2(h, l);
            } else if (cb < 192) {
                int cw = (c - 96) / 2;
                uint32_t h, l;
                bfsplit2(acc[j].x, acc[j].y, h, l); KP[rA * 50 + cw] = make_uint2(h, l);
                bfsplit2(acc[j].z, acc[j].w, h, l); KP[rB * 50 + cw] = make_uint2(h, l);
            } else {
                int d = c - 192;
                __nv_bfloat16 h, l;
                bfsplit1(acc[j].x, h, l); VHs[d * 72 + rA] = h;       VLs[d * 72 + rA] = l;
                bfsplit1(acc[j].y, h, l); VHs[(d + 1) * 72 + rA] = h; VLs[(d + 1) * 72 + rA] = l;
                bfsplit1(acc[j].z, h, l); VHs[d * 72 + rB] = h;       VLs[d * 72 + rB] = l;
                bfsplit1(acc[j].w, h, l); VHs[(d + 1) * 72 + rB] = h; VLs[(d + 1) * 72 + rB] = l;
            }
        }
    }
    __syncthreads();

    // ---- heads: 2 in flight; 8 warps/head; deferred-normalization softmax --
    const int hg = wg >> 3;
    const int w8 = wg & 7;
    const int hm = w8 & 3;
    const int nh = w8 >> 2;

    for (int it = 0; it < 3; it++) {
        const int hd = it * 2 + hg;
        uint2* SPg = SP + hg * (64 * 34);

        // scores + bias; write UNNORMALIZED exp to SP, (m,s) to ST
        {
            float4 acc[4];
            #pragma unroll
            for (int jt = 0; jt < 4; jt++) acc[jt] = make_float4(0.f, 0.f, 0.f, 0.f);
            int qw = (hm * 16 + mg) * 50 + hd * 8 + mt;
            uint2 q0 = QP[qw], q1 = QP[qw + 400], q2 = QP[qw + 4], q3 = QP[qw + 404];
            uint32_t ah[4] = {q0.x, q1.x, q2.x, q3.x};
            uint32_t al[4] = {q0.y, q1.y, q2.y, q3.y};
            #pragma unroll
            for (int jt = 0; jt < 4; jt++) {
                int kw = (nh * 32 + jt * 8 + mg) * 50 + hd * 8 + mt;
                uint2 b0 = KP[kw], b1v = KP[kw + 4];
                mma_bf16(acc[jt], ah, b0.x, b1v.x);
                mma_bf16(acc[jt], ah, b0.y, b1v.y);
                mma_bf16(acc[jt], al, b0.x, b1v.x);
            }
            const int iA = hm * 16 + mg, iB = iA + 8;
            const float4* BP4 = BiasV + hd * 1024 + (hm * 2 + nh) * 128;
            float mA = -1e30f, mB = -1e30f;
            #pragma unroll
            for (int jt = 0; jt < 4; jt++) {
                float4 bf = __ldg(&BP4[jt * 32 + tx]);
                acc[jt].x = fmaf(acc[jt].x, 0.25f, bf.x);
                acc[jt].y = fmaf(acc[jt].y, 0.25f, bf.y);
                acc[jt].z = fmaf(acc[jt].z, 0.25f, bf.z);
                acc[jt].w = fmaf(acc[jt].w, 0.25f, bf.w);
                mA = fmaxf(mA, fmaxf(acc[jt].x, acc[jt].y));
                mB = fmaxf(mB, fmaxf(acc[jt].z, acc[jt].w));
            }
            mA = fmaxf(mA, __shfl_xor_sync(0xffffffffu, mA, 1));
            mA = fmaxf(mA, __shfl_xor_sync(0xffffffffu, mA, 2));
            mB = fmaxf(mB, __shfl_xor_sync(0xffffffffu, mB, 1));
            mB = fmaxf(mB, __shfl_xor_sync(0xffffffffu, mB, 2));
            float sA = 0.f, sB = 0.f;
            #pragma unroll
            for (int jt = 0; jt < 4; jt++) {
                acc[jt].x = fexp(acc[jt].x - mA); acc[jt].y = fexp(acc[jt].y - mA);
                acc[jt].z = fexp(acc[jt].z - mB); acc[jt].w = fexp(acc[jt].w - mB);
                sA += acc[jt].x + acc[jt].y;
                sB += acc[jt].z + acc[jt].w;
            }
            sA += __shfl_xor_sync(0xffffffffu, sA, 1);
            sA += __shfl_xor_sync(0xffffffffu, sA, 2);
            sB += __shfl_xor_sync(0xffffffffu, sB, 1);
            sB += __shfl_xor_sync(0xffffffffu, sB, 2);
            if (mt == 0) {
                ST[((hg * 64 + iA) << 1) | nh] = make_float2(mA, sA);
                ST[((hg * 64 + iB) << 1) | nh] = make_float2(mB, sB);
            }
            #pragma unroll
            for (int jt = 0; jt < 4; jt++) {
                int kw = nh * 16 + jt * 4 + mt;
                uint32_t h, l;
                bfsplit2(acc[jt].x, acc[jt].y, h, l); SPg[iA * 34 + kw] = make_uint2(h, l);
                bfsplit2(acc[jt].z, acc[jt].w, h, l); SPg[iB * 34 + kw] = make_uint2(h, l);
            }
        }
        __syncthreads();

        // AV with per-half accumulators; apply merged scales after sync
        {
            int nc0 = hd * 16 + nh * 8;
            float4 ac0 = make_float4(0.f, 0.f, 0.f, 0.f);   // k halves 0 (cols 0..31)
            float4 ac1 = make_float4(0.f, 0.f, 0.f, 0.f);   // cols 32..63
            #pragma unroll
            for (int ks = 0; ks < 4; ks++) {
                int spw = (hm * 16 + mg) * 34 + ks * 8 + mt;
                uint2 a0 = SPg[spw],     a1 = SPg[spw + 272];
                uint2 a2 = SPg[spw + 4], a3 = SPg[spw + 276];
                uint32_t ah[4] = {a0.x, a1.x, a2.x, a3.x};
                uint32_t al[4] = {a0.y, a1.y, a2.y, a3.y};
                int vw = (nc0 + mg) * 36 + ks * 8 + mt;
                uint32_t bh0 = VH[vw], bh1 = VH[vw + 4];
                uint32_t bl0 = VL[vw], bl1 = VL[vw + 4];
                float4& ac = (ks < 2) ? ac0 : ac1;
                mma_bf16(ac, ah, bh0, bh1);
                mma_bf16(ac, ah, bl0, bl1);
                mma_bf16(ac, al, bh0, bh1);
            }
            int rA = hm * 16 + mg, rB = rA + 8;
            float2 pA0 = ST[(hg * 64 + rA) << 1], pA1 = ST[((hg * 64 + rA) << 1) | 1];
            float2 pB0 = ST[(hg * 64 + rB) << 1], pB1 = ST[((hg * 64 + rB) << 1) | 1];
            float MA = fmaxf(pA0.x, pA1.x);
            float eA0 = fexp(pA0.x - MA), eA1 = fexp(pA1.x - MA);
            float invA = 1.0f / fmaf(pA0.y, eA0, pA1.y * eA1);
            float sc0A = eA0 * invA, sc1A = eA1 * invA;
            float MB = fmaxf(pB0.x, pB1.x);
            float eB0 = fexp(pB0.x - MB), eB1 = fexp(pB1.x - MB);
            float invB = 1.0f / fmaf(pB0.y, eB0, pB1.y * eB1);
            float sc0B = eB0 * invB, sc1B = eB1 * invB;
            float ox = fmaf(sc0A, ac0.x, sc1A * ac1.x);
            float oy = fmaf(sc0A, ac0.y, sc1A * ac1.y);
            float oz = fmaf(sc0B, ac0.z, sc1B * ac1.z);
            float ow = fmaf(sc0B, ac0.w, sc1B * ac1.w);
            int cw = hd * 8 + nh * 4 + mt;
            uint32_t h, l;
            bfsplit2(ox, oy, h, l); OP[rA * 50 + cw] = make_uint2(h, l);
            bfsplit2(oz, ow, h, l); OP[rB * 50 + cw] = make_uint2(h, l);
        }
        __syncthreads();
    }

    // ---- proj + residual -> Y ----
    {
        float4 acc[3];
        #pragma unroll
        for (int j = 0; j < 3; j++) {
            int c = nch * 24 + j * 8 + 2 * mt;
            float b0 = __ldg(&bproj[c]), b1v = __ldg(&bproj[c + 1]);
            acc[j].x = b0; acc[j].y = b1v; acc[j].z = b0; acc[j].w = b1v;
        }
        mma_gemm_pk<3, 6>(acc, OP, 50, m0, WPF, nch * 3, mg, mt, tx);
        #pragma unroll
        for (int j = 0; j < 3; j++) {
            int c = nch * 24 + j * 8 + 2 * mt;
            int cw = c / 2;
            int rA = m0 + mg, rB = rA + 8;
            float xA0, xA1, xB0, xB1;
            bfrec2(XP[rA * 50 + cw], xA0, xA1);
            bfrec2(XP[rB * 50 + cw], xB0, xB1);
            Y[rA * QS + c]     = acc[j].x + xA0;
            Y[rA * QS + c + 1] = acc[j].y + xA1;
            Y[rB * QS + c]     = acc[j].z + xB0;
            Y[rB * QS + c + 1] = acc[j].w + xB1;
        }
    }
    __syncthreads();

    // ---- LayerNorm 1 -> split XP (FFN input) ----
    {
        int row = tid >> 3, l8 = tid & 7;
        float s = 0.f, s2 = 0.f;
        #pragma unroll
        for (int q = 0; q < 3; q++) {
            float4 y = *(const float4*)&Y[row * QS + l8 * 12 + q * 4];
            s += (y.x + y.y) + (y.z + y.w);
            s2 = fmaf(y.x, y.x, fmaf(y.y, y.y, fmaf(y.z, y.z, fmaf(y.w, y.w, s2))));
        }
        #pragma unroll
        for (int o = 4; o > 0; o >>= 1) {
            s  += __shfl_xor_sync(0xffffffffu, s,  o);
            s2 += __shfl_xor_sync(0xffffffffu, s2, o);
        }
        if (l8 == 0) {
            float mean = s * (1.0f / 96.0f);
            float var  = fmaf(-mean, mean, s2 * (1.0f / 96.0f));
            stats[row]      = mean;
            stats[64 + row] = rsqrtf(var + 1e-5f);
        }
    }
    __syncthreads();
    for (int idx = tid; idx < 64 * 48; idx += 512) {
        int t = idx / 48, wd = idx - t * 48;
        float mean = stats[t], rstd = stats[64 + t];
        float y0 = (Y[t * QS + 2 * wd]     - mean) * rstd;
        float y1 = (Y[t * QS + 2 * wd + 1] - mean) * rstd;
        y0 = fmaf(y0, __ldg(&gam1[2 * wd]),     __ldg(&beta1[2 * wd]));
        y1 = fmaf(y1, __ldg(&gam1[2 * wd + 1]), __ldg(&beta1[2 * wd + 1]));
        uint32_t hh, ll;
        bfsplit2(y0, y1, hh, ll);
        XP[t * 50 + wd] = make_uint2(hh, ll);
    }
    __syncthreads();

    // ================= FFN =================
    {
        float4 acc[6];
        #pragma unroll
        for (int j = 0; j < 6; j++) {
            int c = nch * 48 + j * 8 + 2 * mt;
            float v0 = __ldg(&b1[c]), v1 = __ldg(&b1[c + 1]);
            acc[j].x = v0; acc[j].y = v1; acc[j].z = v0; acc[j].w = v1;
        }
        mma_gemm_pk<6, 6>(acc, XP, 50, m0, W1F, nch * 6, mg, mt, tx);
        #pragma unroll
        for (int j = 0; j < 6; j++) {
            int cw = nch * 24 + j * 4 + mt;
            int rA = m0 + mg, rB = rA + 8;
            float g0 = 0.5f * acc[j].x * (1.0f + erff(acc[j].x * 0.70710678118654752f));
            float g1 = 0.5f * acc[j].y * (1.0f + erff(acc[j].y * 0.70710678118654752f));
            float g2 = 0.5f * acc[j].z * (1.0f + erff(acc[j].z * 0.70710678118654752f));
            float g3 = 0.5f * acc[j].w * (1.0f + erff(acc[j].w * 0.70710678118654752f));
            uint32_t h, l;
            bfsplit2(g0, g1, h, l); HP[rA * 98 + cw] = make_uint2(h, l);
            bfsplit2(g2, g3, h, l); HP[rB * 98 + cw] = make_uint2(h, l);
        }
    }
    __syncthreads();

    {
        float4 acc[3];
        #pragma unroll
        for (int j = 0; j < 3; j++) {
            int c = nch * 24 + j * 8 + 2 * mt;
            float v0 = __ldg(&b2[c]), v1 = __ldg(&b2[c + 1]);
            acc[j].x = v0; acc[j].y = v1; acc[j].z = v0; acc[j].w = v1;
        }
        mma_gemm_pk<3, 12>(acc, HP, 98, m0, W2F, nch * 3, mg, mt, tx);
        #pragma unroll
        for (int j = 0; j < 3; j++) {
            int c = nch * 24 + j * 8 + 2 * mt;
            int cw = c / 2;
            int rA = m0 + mg, rB = rA + 8;
            float xA0, xA1, xB0, xB1;
            bfrec2(XP[rA * 50 + cw], xA0, xA1);
            bfrec2(XP[rB * 50 + cw], xB0, xB1);
            Y[rA * QS + c]     = acc[j].x + xA0;
            Y[rA * QS + c + 1] = acc[j].y + xA1;
            Y[rB * QS + c]     = acc[j].z + xB0;
            Y[rB * QS + c + 1] = acc[j].w + xB1;
        }
    }
    __syncthreads();

    // ---- LayerNorm 2 + scatter (split-plane output) ----
    {
        int row = tid >> 3, l8 = tid & 7;
        float s = 0.f, s2 = 0.f;
        #pragma unroll
        for (int q = 0; q < 3; q++) {
            float4 y = *(const float4*)&Y[row * QS + l8 * 12 + q * 4];
            s += (y.x + y.y) + (y.z + y.w);
            s2 = fmaf(y.x, y.x, fmaf(y.y, y.y, fmaf(y.z, y.z, fmaf(y.w, y.w, s2))));
        }
        #pragma unroll
        for (int o = 4; o > 0; o >>= 1) {
            s  += __shfl_xor_sync(0xffffffffu, s,  o);
            s2 += __shfl_xor_sync(0xffffffffu, s2, o);
        }
        if (l8 == 0) {
            float mean = s * (1.0f / 96.0f);
            float var  = fmaf(-mean, mean, s2 * (1.0f / 96.0f));
            stats[row]      = mean;
            stats[64 + row] = rsqrtf(var + 1e-5f);
        }
    }
    __syncthreads();

    for (int idx = tid; idx < 64 * 48; idx += 512) {
        int t = idx / 48, wd = idx - t * 48;
        int r = t >> 3, cl = t & 7;
        int h = wr * 8 + r, w = wc * 8 + cl;
        if (SHIFTED) { h += 4; if (h >= HH) h -= HH; w += 4; if (w >= WWI) w -= WWI; }
        float mean = stats[t], rstd = stats[64 + t];
        float y0 = (Y[t * QS + 2 * wd]     - mean) * rstd;
        float y1 = (Y[t * QS + 2 * wd + 1] - mean) * rstd;
        y0 = fmaf(y0, __ldg(&gam2[2 * wd]),     __ldg(&beta2[2 * wd]));
        y1 = fmaf(y1, __ldg(&gam2[2 * wd + 1]), __ldg(&beta2[2 * wd + 1]));
        uint32_t hh, ll;
        bfsplit2(y0, y1, hh, ll);
        dst[(size_t)(h * WWI + w) * 48 + wd] = make_uint2(hh, ll);
    }
}

// ---------------------------------------------------------------------------
// Input order (setup_inputs dict order):
//   0: x | 1..7: sa1 | 8..14: sa2 | 15..20: ff1 | 21..26: ff2
// ---------------------------------------------------------------------------
extern "C" void kernel_launch(void* const* d_in, const int* in_sizes, int n_in,
                              void* d_out, int out_size) {
    const float* x = (const float*)d_in[0];
    uint2 *imgA, *imgB;
    uint4* wf;
    float4* bias;
    cudaGetSymbolAddress((void**)&imgA, g_imgA);
    cudaGetSymbolAddress((void**)&imgB, g_imgB);
    cudaGetSymbolAddress((void**)&wf,   g_wfrag);
    cudaGetSymbolAddress((void**)&bias, g_bias4);

    cudaFuncSetAttribute(block_kernel<0>, cudaFuncAttributeMaxDynamicSharedMemorySize, BLK_SMEM);
    cudaFuncSetAttribute(block_kernel<1>, cudaFuncAttributeMaxDynamicSharedMemorySize, BLK_SMEM);

    split_all_weights<<<dim3(27, 8), 256>>>(
        (const float*)d_in[1],  (const float*)d_in[4],
        (const float*)d_in[8],  (const float*)d_in[11],
        (const float*)d_in[15], (const float*)d_in[21],
        (const float*)d_in[17], (const float*)d_in[23]);

    build_bias<<<dim3(96, 2), 256>>>((const float*)d_in[3], (const float*)d_in[10]);

    dim3 tb(32, 8);
    dim3 tg(HW / 32, CH / 32, BATCH);

    transpose_in_kernel<<<tg, tb>>>(x, imgA);

    block_kernel<0><<<NWIN, 512, BLK_SMEM>>>(
        imgA, imgB, wf + WF_SA1_QKV,
        (const float*)d_in[2], bias,
        wf + WF_SA1_PROJ, (const float*)d_in[5],
        (const float*)d_in[6], (const float*)d_in[7],
        wf + WF_FF1_W1, (const float*)d_in[16],
        wf + WF_FF1_W2, (const float*)d_in[18],
        (const float*)d_in[19], (const float*)d_in[20]);

    block_kernel<1><<<NWIN, 512, BLK_SMEM>>>(
        imgB, imgA, wf + WF_SA2_QKV,
        (const float*)d_in[9], bias + 24576,
        wf + WF_SA2_PROJ, (const float*)d_in[12],
        (const float*)d_in[13], (const float*)d_in[14],
        wf + WF_FF2_W1, (const float*)d_in[22],
        wf + WF_FF2_W2, (const float*)d_in[24],
        (const float*)d_in[25], (const float*)d_in[26]);

    transpose_out_kernel<<<tg, tb>>>(imgA, (float*)d_out);
}